// round 15
// baseline (speedup 1.0000x reference)
#include <cuda_runtime.h>
#include <cuda_bf16.h>
#include <cuda_fp16.h>
#include <cstdint>

// Problem constants
#define BATCH   2
#define SEQ     2048
#define DIN     1024
#define DOUT    1024
#define NHEADS  16
#define HDIM    64
#define MROWS   (BATCH * SEQ)        // 4096
#define WELEM   (DIN * DOUT)         // 1M

// ---------------------------------------------------------------------------
// Scratch (device globals — no runtime allocation allowed)
// ---------------------------------------------------------------------------
__device__ __half g_xh[MROWS * DIN];         // x fp16
__device__ __half g_Wt[4 * WELEM];           // transposed weights [N,K], fp16
__device__ __half g_Qh[MROWS * DOUT];
__device__ __half g_Ql[MROWS * DOUT];        // Q lo (S stays 2-term)
__device__ __half g_Kh[MROWS * DOUT];        // K hi only
__device__ __half g_Vh[MROWS * DOUT];        // V hi only
__device__ __half g_Ch[MROWS * DOUT];        // ctx fp16 (hi only)

// ---------------------------------------------------------------------------
// Warp-MMA / async-copy helpers (baseline PTX ISA, no arch-"a" features)
// ---------------------------------------------------------------------------
__device__ __forceinline__ uint32_t smem_u32(const void* p) {
    uint32_t a;
    asm("{ .reg .u64 t; cvta.to.shared.u64 t, %1; cvt.u32.u64 %0, t; }"
        : "=r"(a) : "l"(p));
    return a;
}
__device__ __forceinline__ void ldsm4(uint32_t* r, uint32_t addr) {
    asm volatile("ldmatrix.sync.aligned.m8n8.x4.shared.b16 {%0,%1,%2,%3}, [%4];"
                 : "=r"(r[0]), "=r"(r[1]), "=r"(r[2]), "=r"(r[3]) : "r"(addr));
}
__device__ __forceinline__ void ldsm4t(uint32_t* r, uint32_t addr) {
    asm volatile("ldmatrix.sync.aligned.m8n8.x4.trans.shared.b16 {%0,%1,%2,%3}, [%4];"
                 : "=r"(r[0]), "=r"(r[1]), "=r"(r[2]), "=r"(r[3]) : "r"(addr));
}
__device__ __forceinline__ void mma_f16(float* c, const uint32_t* a,
                                        uint32_t b0, uint32_t b1) {
    asm volatile(
        "mma.sync.aligned.m16n8k16.row.col.f32.f16.f16.f32 "
        "{%0,%1,%2,%3}, {%4,%5,%6,%7}, {%8,%9}, {%0,%1,%2,%3};"
        : "+f"(c[0]), "+f"(c[1]), "+f"(c[2]), "+f"(c[3])
        : "r"(a[0]), "r"(a[1]), "r"(a[2]), "r"(a[3]), "r"(b0), "r"(b1));
}
__device__ __forceinline__ void cp16(uint32_t dst, const void* src) {
    asm volatile("cp.async.cg.shared.global [%0], [%1], 16;"
                 :: "r"(dst), "l"(src));
}
#define CP_COMMIT() asm volatile("cp.async.commit_group;" ::: "memory")
#define CP_WAIT1()  asm volatile("cp.async.wait_group 1;" ::: "memory")
#define CP_WAIT0()  asm volatile("cp.async.wait_group 0;" ::: "memory")

__device__ __forceinline__ uint32_t pack_h2(__half a, __half b) {
    __half2 h = __halves2half2(a, b);
    return *reinterpret_cast<uint32_t*>(&h);
}

// ---------------------------------------------------------------------------
// Convert fp32 -> fp16
// ---------------------------------------------------------------------------
__global__ __launch_bounds__(256)
void convert_half_kernel(const float* __restrict__ in, __half* __restrict__ o, int n4)
{
    int i = blockIdx.x * blockDim.x + threadIdx.x;
    if (i >= n4) return;
    float4 v = reinterpret_cast<const float4*>(in)[i];
    uint2 p = make_uint2(pack_h2(__float2half_rn(v.x), __float2half_rn(v.y)),
                         pack_h2(__float2half_rn(v.z), __float2half_rn(v.w)));
    reinterpret_cast<uint2*>(o)[i] = p;
}

// ---------------------------------------------------------------------------
// Transpose: W [K,N] fp32 row-major -> Wt [N,K] fp16 (4 matrices via z)
// ---------------------------------------------------------------------------
__global__ __launch_bounds__(256)
void transpose_half_kernel(const float* const* __restrict__ Ws,
                           __half* __restrict__ T)
{
    __shared__ float t[32][33];
    const float* W = Ws[blockIdx.z];
    __half* To = T + (size_t)blockIdx.z * WELEM;
    int bx = blockIdx.x * 32;   // N
    int by = blockIdx.y * 32;   // K
    int x = threadIdx.x, y = threadIdx.y;
    #pragma unroll
    for (int j = 0; j < 32; j += 8)
        t[y + j][x] = W[(size_t)(by + y + j) * DOUT + bx + x];
    __syncthreads();
    #pragma unroll
    for (int j = 0; j < 32; j += 8)
        To[(size_t)(bx + y + j) * DIN + by + x] = __float2half_rn(t[x][y + j]);
}
__device__ const float* g_Wptrs[4];
__global__ void set_wptrs_kernel(const float* a, const float* b,
                                 const float* c, const float* d)
{
    g_Wptrs[0] = a; g_Wptrs[1] = b; g_Wptrs[2] = c; g_Wptrs[3] = d;
}

// ---------------------------------------------------------------------------
// 3-stage cp.async HMMA GEMM, 1-term fp16.  128x128x32, one barrier/iter.
// QKV=true : fused N=3072; epilogue emits Q hi/lo (x0.125), K hi, V hi.
// QKV=false: fp32 + bias epilogue (output projection).
// ---------------------------------------------------------------------------
#define CTM 128
#define CTN 128
#define CTK 32
#define GKIT (DIN / CTK)             // 32
#define TENB 10240                   // bytes per tensor tile (128 rows * 80 B)
#define TO_B TENB
#define STAGE (2 * TENB)             // 20480
#define GEMM_SMEM (3 * STAGE)        // 61440

template<bool QKV>
__global__ __launch_bounds__(256, 2)
void gemm_pipe(const __half* __restrict__ Ah, const __half* __restrict__ Bh,
               const float* __restrict__ bias, float* __restrict__ C,
               __half* __restrict__ O0h, __half* __restrict__ O0l,
               __half* __restrict__ O1h, __half* __restrict__ O2h)
{
    extern __shared__ __align__(16) char sm_raw[];
    const uint32_t su = smem_u32(sm_raw);

    const int tid  = threadIdx.x;
    const int w    = tid >> 5;
    const int lane = tid & 31;
    const int wm   = w >> 2;            // 0..1
    const int wn   = w & 3;             // 0..3
    const int bm   = blockIdx.y * CTM;
    const int bn   = blockIdx.x * CTN;

    const int arow = wm * 64 + (lane & 15);
    const int brow = wn * 32 + (lane & 15);
    const int khalf = (lane >> 4) * 8;

    float acc[4][4][4];
    #pragma unroll
    for (int mt = 0; mt < 4; mt++)
        #pragma unroll
        for (int nt = 0; nt < 4; nt++)
            #pragma unroll
            for (int e = 0; e < 4; e++) acc[mt][nt][e] = 0.f;

    #define ISSUE(it_, buf_) do {                                              \
        const int k0_ = (it_) * CTK;                                           \
        const uint32_t sb_ = su + (buf_) * STAGE;                              \
        _Pragma("unroll")                                                      \
        for (int t = 0; t < 2; t++) {                                          \
            int u = tid + t * 256;                                             \
            int row = u >> 2, cs = u & 3;                                      \
            size_t ga = (size_t)(bm + row) * 1024 + k0_ + cs * 8;              \
            size_t gb = (size_t)(bn + row) * 1024 + k0_ + cs * 8;              \
            uint32_t off = row * 80 + cs * 16;                                 \
            cp16(sb_ + off, Ah + ga);                                          \
            cp16(sb_ + TO_B + off, Bh + gb);                                   \
        }                                                                      \
    } while (0)

    ISSUE(0, 0); CP_COMMIT();
    ISSUE(1, 1); CP_COMMIT();

    for (int it = 0; it < GKIT; it++) {
        if (it + 1 < GKIT) CP_WAIT1(); else CP_WAIT0();
        __syncthreads();
        if (it + 2 < GKIT) {
            ISSUE(it + 2, (it + 2) % 3);
            CP_COMMIT();
        }

        const uint32_t sb = su + (it % 3) * STAGE;

        #pragma unroll
        for (int ks = 0; ks < 2; ks++) {
            const int kb = ks * 16 + khalf;
            uint32_t bh[8];
            ldsm4(bh + 0, sb + TO_B + (brow +  0) * 80 + kb * 2);
            ldsm4(bh + 4, sb + TO_B + (brow + 16) * 80 + kb * 2);

            #pragma unroll
            for (int mt = 0; mt < 4; mt++) {
                uint32_t ah[4];
                ldsm4(ah, sb + (arow + mt * 16) * 80 + kb * 2);
                #pragma unroll
                for (int nt = 0; nt < 4; nt++) {
                    const int i0 = 4 * (nt >> 1) + (nt & 1);
                    mma_f16(acc[mt][nt], ah, bh[i0], bh[i0 + 2]);
                }
            }
        }
    }
    #undef ISSUE

    const int erow = bm + wm * 64 + (lane >> 2);

    if (QKV) {
        const int tsel = bn >> 10;              // 0=Q, 1=K, 2=V
        const int cloc = (bn & 1023) + wn * 32;
        __half* Oh = (tsel == 0) ? O0h : (tsel == 1) ? O1h : O2h;
        const bool wlo = (tsel == 0);
        const float scl = (tsel == 0) ? 0.125f : 1.0f;
        #pragma unroll
        for (int nt = 0; nt < 4; nt++) {
            const int col = cloc + nt * 8 + (lane & 3) * 2;
            #pragma unroll
            for (int mt = 0; mt < 4; mt++) {
                #pragma unroll
                for (int rh = 0; rh < 2; rh++) {
                    const size_t row = (size_t)(erow + mt * 16 + rh * 8);
                    const float v0 = acc[mt][nt][2 * rh]     * scl;
                    const float v1 = acc[mt][nt][2 * rh + 1] * scl;
                    const __half h0 = __float2half_rn(v0);
                    const __half h1 = __float2half_rn(v1);
                    *reinterpret_cast<uint32_t*>(Oh + row * 1024 + col) = pack_h2(h0, h1);
                    if (wlo) {
                        const __half l0 = __float2half_rn(v0 - __half2float(h0));
                        const __half l1 = __float2half_rn(v1 - __half2float(h1));
                        *reinterpret_cast<uint32_t*>(O0l + row * 1024 + col) = pack_h2(l0, l1);
                    }
                }
            }
        }
    } else {
        #pragma unroll
        for (int nt = 0; nt < 4; nt++) {
            const int col = bn + wn * 32 + nt * 8 + (lane & 3) * 2;
            const float bx = bias ? bias[col] : 0.f;
            const float by = bias ? bias[col + 1] : 0.f;
            #pragma unroll
            for (int mt = 0; mt < 4; mt++) {
                const int r0 = erow + mt * 16;
                float2 v0 = make_float2(acc[mt][nt][0] + bx, acc[mt][nt][1] + by);
                float2 v1 = make_float2(acc[mt][nt][2] + bx, acc[mt][nt][3] + by);
                *reinterpret_cast<float2*>(C + (size_t)r0 * DOUT + col) = v0;
                *reinterpret_cast<float2*>(C + (size_t)(r0 + 8) * DOUT + col) = v1;
            }
        }
    }
}

// ---------------------------------------------------------------------------
// HMMA flash attention.  S: 2-term (Q hi/lo, K hi).  PV: 1-term.
// 3-buffer cp.async KV pipeline, one barrier per kv tile, 2 CTAs/SM.
// ---------------------------------------------------------------------------
#define ABQ 128
#define AKV 64
#define AST 72
#define KVT_H (AKV * AST)               // 4608 halves
#define STAGE_H (2 * KVT_H)             // Kh | Vh (9216 halves)
#define ASMEM_B (3 * STAGE_H * 2)       // 55296 bytes

__global__ __launch_bounds__(256, 2)
void attn_mma(const __half* __restrict__ Qh, const __half* __restrict__ Ql,
              const __half* __restrict__ Kh, const __half* __restrict__ Vh,
              __half* __restrict__ Ch)
{
    extern __shared__ __align__(16) __half s[];
    const uint32_t sbase = smem_u32(s);

    const int tid  = threadIdx.x;
    const int w    = tid >> 5;
    const int lane = tid & 31;

    const int qt = (int)gridDim.x - 1 - (int)blockIdx.x;   // heavy first
    const int bh = blockIdx.y;
    const int b  = bh >> 4;
    const int h  = bh & 15;

    const size_t rowbase = (size_t)b * SEQ;
    const int    colbase = h * HDIM;
    const int    qbase   = qt * ABQ;
    const int    wq      = qbase + w * 16;

    // ---- stage Q hi/lo (generic stores), load A fragments ----
    {
        #pragma unroll
        for (int t = 0; t < 4; t++) {
            int u = tid + t * 256;
            int row = u >> 3, seg = u & 7;
            uint4 vh4 = *reinterpret_cast<const uint4*>(
                Qh + (rowbase + qbase + row) * 1024 + colbase + seg * 8);
            uint4 vl4 = *reinterpret_cast<const uint4*>(
                Ql + (rowbase + qbase + row) * 1024 + colbase + seg * 8);
            *reinterpret_cast<uint4*>(s + row * AST + seg * 8) = vh4;
            *reinterpret_cast<uint4*>(s + ABQ * AST + row * AST + seg * 8) = vl4;
        }
    }
    __syncthreads();

    uint32_t qfh[4][4], qfl[4][4];
    {
        const int arow = w * 16 + (lane & 15);
        const int k8   = (lane >> 4) * 8;
        #pragma unroll
        for (int ks = 0; ks < 4; ks++) {
            ldsm4(qfh[ks], sbase + (arow * AST + ks * 16 + k8) * 2);
            ldsm4(qfl[ks], sbase + ((ABQ * AST) + arow * AST + ks * 16 + k8) * 2);
        }
    }
    __syncthreads();   // all warps done reading Q region before cp.async overwrites

    float ctx[8][4];
    #pragma unroll
    for (int nt = 0; nt < 8; nt++)
        #pragma unroll
        for (int e = 0; e < 4; e++) ctx[nt][e] = 0.f;
    float mrow[2] = {-1e30f, -1e30f};
    float lrow[2] = {0.f, 0.f};

    const int nkt = 2 * qt + 2;

    // cp.async KV tile load: 2 tensors x 64 rows x 128 B = 1024 x 16B segs
    #define AISSUE(kt_, buf_) do {                                             \
        const __half* gt0[2] = {Kh, Vh};                                       \
        const uint32_t sb_ = sbase + (buf_) * STAGE_H * 2;                     \
        _Pragma("unroll")                                                      \
        for (int tn = 0; tn < 2; tn++)                                         \
            _Pragma("unroll")                                                  \
            for (int t = 0; t < 2; t++) {                                      \
                int u = tid + t * 256;                                         \
                int row = u >> 3, seg = u & 7;                                 \
                cp16(sb_ + (tn * KVT_H + row * AST + seg * 8) * 2,             \
                     gt0[tn] + (rowbase + (kt_) * AKV + row) * 1024            \
                             + colbase + seg * 8);                             \
            }                                                                  \
    } while (0)

    AISSUE(0, 0); CP_COMMIT();
    if (nkt > 1) { AISSUE(1, 1); CP_COMMIT(); }

    for (int kt = 0; kt < nkt; kt++) {
        if (kt + 1 < nkt) CP_WAIT1(); else CP_WAIT0();
        __syncthreads();
        if (kt + 2 < nkt) {
            AISSUE(kt + 2, (kt + 2) % 3);
            CP_COMMIT();
        }

        const bool skip = (kt * AKV) > (wq + 15);
        if (!skip) {
            const int buf = kt % 3;
            const uint32_t kh_b = sbase + (buf * STAGE_H + 0 * KVT_H) * 2;
            const uint32_t vh_b = sbase + (buf * STAGE_H + 1 * KVT_H) * 2;

            // ---- S = Q K^T (2-term: Q corrected) ----
            float sv[8][4];
            #pragma unroll
            for (int nt = 0; nt < 8; nt++)
                #pragma unroll
                for (int e = 0; e < 4; e++) sv[nt][e] = 0.f;

            const int brow = lane & 15;
            const int k8   = (lane >> 4) * 8;
            #pragma unroll
            for (int ks = 0; ks < 4; ks++) {
                #pragma unroll
                for (int np = 0; np < 4; np++) {
                    uint32_t kh4[4];
                    const uint32_t off = ((np * 16 + brow) * AST + ks * 16 + k8) * 2;
                    ldsm4(kh4, kh_b + off);
                    mma_f16(sv[2 * np],     qfh[ks], kh4[0], kh4[2]);
                    mma_f16(sv[2 * np],     qfl[ks], kh4[0], kh4[2]);
                    mma_f16(sv[2 * np + 1], qfh[ks], kh4[1], kh4[3]);
                    mma_f16(sv[2 * np + 1], qfl[ks], kh4[1], kh4[3]);
                }
            }

            // ---- causal mask ----
            if (kt * AKV + AKV - 1 > wq) {
                const int qr = wq + (lane >> 2);
                #pragma unroll
                for (int nt = 0; nt < 8; nt++) {
                    const int kg0 = kt * AKV + nt * 8 + (lane & 3) * 2;
                    #pragma unroll
                    for (int e = 0; e < 4; e++) {
                        const int qg = qr + ((e >> 1) << 3);
                        const int kg = kg0 + (e & 1);
                        if (kg > qg) sv[nt][e] = -1e30f;
                    }
                }
            }

            // ---- online softmax ----
            float alpha[2];
            #pragma unroll
            for (int rr = 0; rr < 2; rr++) {
                float rmax = -1e30f;
                #pragma unroll
                for (int nt = 0; nt < 8; nt++)
                    rmax = fmaxf(rmax, fmaxf(sv[nt][2 * rr], sv[nt][2 * rr + 1]));
                rmax = fmaxf(rmax, __shfl_xor_sync(0xffffffffu, rmax, 1));
                rmax = fmaxf(rmax, __shfl_xor_sync(0xffffffffu, rmax, 2));
                const float mnew = fmaxf(mrow[rr], rmax);
                alpha[rr] = __expf(mrow[rr] - mnew);
                float rsum = 0.f;
                #pragma unroll
                for (int nt = 0; nt < 8; nt++) {
                    float p0 = __expf(sv[nt][2 * rr]     - mnew);
                    float p1 = __expf(sv[nt][2 * rr + 1] - mnew);
                    sv[nt][2 * rr] = p0; sv[nt][2 * rr + 1] = p1;
                    rsum += p0 + p1;
                }
                rsum += __shfl_xor_sync(0xffffffffu, rsum, 1);
                rsum += __shfl_xor_sync(0xffffffffu, rsum, 2);
                lrow[rr] = lrow[rr] * alpha[rr] + rsum;
                mrow[rr] = mnew;
            }
            #pragma unroll
            for (int nt = 0; nt < 8; nt++) {
                ctx[nt][0] *= alpha[0]; ctx[nt][1] *= alpha[0];
                ctx[nt][2] *= alpha[1]; ctx[nt][3] *= alpha[1];
            }

            // ---- pack P fragments (fp16 hi only) ----
            uint32_t pah[4][4];
            #pragma unroll
            for (int t = 0; t < 4; t++) {
                #pragma unroll
                for (int h2 = 0; h2 < 4; h2++) {
                    const int nt = 2 * t + (h2 >> 1);
                    const int e0 = (h2 & 1) * 2;
                    pah[t][h2] = pack_h2(__float2half_rn(sv[nt][e0]),
                                         __float2half_rn(sv[nt][e0 + 1]));
                }
            }

            // ---- ctx += P V (1-term) ----
            #pragma unroll
            for (int t = 0; t < 4; t++) {
                #pragma unroll
                for (int dp = 0; dp < 4; dp++) {
                    uint32_t vh4[4];
                    const uint32_t off =
                        ((t * 16 + (lane & 15)) * AST + dp * 16 + k8) * 2;
                    ldsm4t(vh4, vh_b + off);
                    mma_f16(ctx[2 * dp],     pah[t], vh4[0], vh4[1]);
                    mma_f16(ctx[2 * dp + 1], pah[t], vh4[2], vh4[3]);
                }
            }
        }
    }
    #undef AISSUE

    // ---- epilogue: ctx /= l, write fp16 hi ----
    #pragma unroll
    for (int rr = 0; rr < 2; rr++) {
        const float inv = 1.f / lrow[rr];
        const size_t row = rowbase + qbase + w * 16 + (lane >> 2) + rr * 8;
        #pragma unroll
        for (int nt = 0; nt < 8; nt++) {
            const int col = colbase + nt * 8 + (lane & 3) * 2;
            *reinterpret_cast<uint32_t*>(Ch + row * 1024 + col) =
                pack_h2(__float2half_rn(ctx[nt][2 * rr] * inv),
                        __float2half_rn(ctx[nt][2 * rr + 1] * inv));
        }
    }
}

// ---------------------------------------------------------------------------
// Launcher
// ---------------------------------------------------------------------------
extern "C" void kernel_launch(void* const* d_in, const int* in_sizes, int n_in,
                              void* d_out, int out_size)
{
    const float* x  = (const float*)d_in[0];
    const float* Wq = (const float*)d_in[1];
    const float* Wk = (const float*)d_in[2];
    const float* Wv = (const float*)d_in[3];
    const float* Wo = (const float*)d_in[4];
    const float* bo = (const float*)d_in[5];
    float* out = (float*)d_out;

    __half *xh, *Wt, *qhh, *qhl, *khh, *vhh, *chh;
    cudaGetSymbolAddress((void**)&xh,  g_xh);
    cudaGetSymbolAddress((void**)&Wt,  g_Wt);
    cudaGetSymbolAddress((void**)&qhh, g_Qh);
    cudaGetSymbolAddress((void**)&qhl, g_Ql);
    cudaGetSymbolAddress((void**)&khh, g_Kh);
    cudaGetSymbolAddress((void**)&vhh, g_Vh);
    cudaGetSymbolAddress((void**)&chh, g_Ch);
    const float** wptrs;
    cudaGetSymbolAddress((void**)&wptrs, g_Wptrs);

    const int n4 = MROWS * DIN / 4;

    // convert x -> fp16
    convert_half_kernel<<<(n4 + 255) / 256, 256>>>(x, xh, n4);

    // transpose the four weight matrices to fp16 [N,K] (one launch)
    set_wptrs_kernel<<<1, 1>>>(Wq, Wk, Wv, Wo);
    dim3 tb(32, 8), tg(32, 32, 4);
    transpose_half_kernel<<<tg, tb>>>(wptrs, Wt);

    // fused QKV GEMM (N = 3072), 1-term fp16
    cudaFuncSetAttribute(gemm_pipe<true>,
                         cudaFuncAttributeMaxDynamicSharedMemorySize, GEMM_SMEM);
    cudaFuncSetAttribute(gemm_pipe<false>,
                         cudaFuncAttributeMaxDynamicSharedMemorySize, GEMM_SMEM);
    dim3 gq(3 * DOUT / CTN, MROWS / CTM);   // (24, 32)
    gemm_pipe<true><<<gq, 256, GEMM_SMEM>>>(xh, Wt, nullptr, nullptr,
                                            qhh, qhl, khh, vhh);

    // HMMA flash attention -> fp16 ctx
    cudaFuncSetAttribute(attn_mma, cudaFuncAttributeMaxDynamicSharedMemorySize,
                         ASMEM_B);
    dim3 attn_grid(SEQ / ABQ, BATCH * NHEADS);   // (16, 32)
    attn_mma<<<attn_grid, 256, ASMEM_B>>>(qhh, qhl, khh, vhh, chh);

    // output projection (1-term ctx, with bias)
    dim3 go(DOUT / CTN, MROWS / CTM);       // (8, 32)
    gemm_pipe<false><<<go, 256, GEMM_SMEM>>>(chh, Wt + 3 * WELEM,
                                             bo, out,
                                             nullptr, nullptr, nullptr, nullptr);
}

// round 16
// speedup vs baseline: 1.0923x; 1.0923x over previous
#include <cuda_runtime.h>
#include <cuda_bf16.h>
#include <cuda_fp16.h>
#include <cstdint>

// Problem constants
#define BATCH   2
#define SEQ     2048
#define DIN     1024
#define DOUT    1024
#define NHEADS  16
#define HDIM    64
#define MROWS   (BATCH * SEQ)        // 4096
#define WELEM   (DIN * DOUT)         // 1M

// ---------------------------------------------------------------------------
// Scratch (device globals — no runtime allocation allowed)
// ---------------------------------------------------------------------------
__device__ __half g_xh[MROWS * DIN];         // x fp16
__device__ __half g_Wt[4 * WELEM];           // transposed weights [N,K], fp16
__device__ __half g_Qh[MROWS * DOUT];
__device__ __half g_Ql[MROWS * DOUT];        // Q lo (S stays 2-term)
__device__ __half g_Kh[MROWS * DOUT];        // K hi only
__device__ __half g_Vh[MROWS * DOUT];        // V hi only
__device__ __half g_Ch[MROWS * DOUT];        // ctx fp16 (hi only)

// ---------------------------------------------------------------------------
// Warp-MMA / async-copy helpers (baseline PTX ISA, no arch-"a" features)
// ---------------------------------------------------------------------------
__device__ __forceinline__ uint32_t smem_u32(const void* p) {
    uint32_t a;
    asm("{ .reg .u64 t; cvta.to.shared.u64 t, %1; cvt.u32.u64 %0, t; }"
        : "=r"(a) : "l"(p));
    return a;
}
__device__ __forceinline__ void ldsm4(uint32_t* r, uint32_t addr) {
    asm volatile("ldmatrix.sync.aligned.m8n8.x4.shared.b16 {%0,%1,%2,%3}, [%4];"
                 : "=r"(r[0]), "=r"(r[1]), "=r"(r[2]), "=r"(r[3]) : "r"(addr));
}
__device__ __forceinline__ void ldsm4t(uint32_t* r, uint32_t addr) {
    asm volatile("ldmatrix.sync.aligned.m8n8.x4.trans.shared.b16 {%0,%1,%2,%3}, [%4];"
                 : "=r"(r[0]), "=r"(r[1]), "=r"(r[2]), "=r"(r[3]) : "r"(addr));
}
__device__ __forceinline__ void mma_f16(float* c, const uint32_t* a,
                                        uint32_t b0, uint32_t b1) {
    asm volatile(
        "mma.sync.aligned.m16n8k16.row.col.f32.f16.f16.f32 "
        "{%0,%1,%2,%3}, {%4,%5,%6,%7}, {%8,%9}, {%0,%1,%2,%3};"
        : "+f"(c[0]), "+f"(c[1]), "+f"(c[2]), "+f"(c[3])
        : "r"(a[0]), "r"(a[1]), "r"(a[2]), "r"(a[3]), "r"(b0), "r"(b1));
}
__device__ __forceinline__ void cp16(uint32_t dst, const void* src) {
    asm volatile("cp.async.cg.shared.global [%0], [%1], 16;"
                 :: "r"(dst), "l"(src));
}
#define CP_COMMIT() asm volatile("cp.async.commit_group;" ::: "memory")
#define CP_WAIT1()  asm volatile("cp.async.wait_group 1;" ::: "memory")
#define CP_WAIT0()  asm volatile("cp.async.wait_group 0;" ::: "memory")

__device__ __forceinline__ uint32_t pack_h2(__half a, __half b) {
    __half2 h = __halves2half2(a, b);
    return *reinterpret_cast<uint32_t*>(&h);
}

// ---------------------------------------------------------------------------
// Convert fp32 -> fp16
// ---------------------------------------------------------------------------
__global__ __launch_bounds__(256)
void convert_half_kernel(const float* __restrict__ in, __half* __restrict__ o, int n4)
{
    int i = blockIdx.x * blockDim.x + threadIdx.x;
    if (i >= n4) return;
    float4 v = reinterpret_cast<const float4*>(in)[i];
    uint2 p = make_uint2(pack_h2(__float2half_rn(v.x), __float2half_rn(v.y)),
                         pack_h2(__float2half_rn(v.z), __float2half_rn(v.w)));
    reinterpret_cast<uint2*>(o)[i] = p;
}

// ---------------------------------------------------------------------------
// Transpose: W [K,N] fp32 row-major -> Wt [N,K] fp16 (4 matrices via z)
// ---------------------------------------------------------------------------
__global__ __launch_bounds__(256)
void transpose_half_kernel(const float* const* __restrict__ Ws,
                           __half* __restrict__ T)
{
    __shared__ float t[32][33];
    const float* W = Ws[blockIdx.z];
    __half* To = T + (size_t)blockIdx.z * WELEM;
    int bx = blockIdx.x * 32;   // N
    int by = blockIdx.y * 32;   // K
    int x = threadIdx.x, y = threadIdx.y;
    #pragma unroll
    for (int j = 0; j < 32; j += 8)
        t[y + j][x] = W[(size_t)(by + y + j) * DOUT + bx + x];
    __syncthreads();
    #pragma unroll
    for (int j = 0; j < 32; j += 8)
        To[(size_t)(bx + y + j) * DIN + by + x] = __float2half_rn(t[x][y + j]);
}
__device__ const float* g_Wptrs[4];
__global__ void set_wptrs_kernel(const float* a, const float* b,
                                 const float* c, const float* d)
{
    g_Wptrs[0] = a; g_Wptrs[1] = b; g_Wptrs[2] = c; g_Wptrs[3] = d;
}

// ---------------------------------------------------------------------------
// 2-stage cp.async HMMA GEMM, 1-term fp16.  CTA 128x128, K-tile 64 (16 iters).
// smem row stride 144 B (64 halves + 8 pad) — ldsm conflict-free.
// QKV=true : fused N=3072; epilogue emits Q hi/lo (x0.125), K hi, V hi.
// QKV=false: fp32 + bias epilogue (output projection).
// ---------------------------------------------------------------------------
#define CTM 128
#define CTN 128
#define CTK 64
#define GKIT (DIN / CTK)             // 16
#define GST  144                     // smem row stride (bytes)
#define TENB (128 * GST)             // 18432 bytes per tensor tile
#define TO_B TENB
#define STAGE (2 * TENB)             // 36864
#define GEMM_SMEM (2 * STAGE)        // 73728

template<bool QKV>
__global__ __launch_bounds__(256, 2)
void gemm_pipe(const __half* __restrict__ Ah, const __half* __restrict__ Bh,
               const float* __restrict__ bias, float* __restrict__ C,
               __half* __restrict__ O0h, __half* __restrict__ O0l,
               __half* __restrict__ O1h, __half* __restrict__ O2h)
{
    extern __shared__ __align__(16) char sm_raw[];
    const uint32_t su = smem_u32(sm_raw);

    const int tid  = threadIdx.x;
    const int w    = tid >> 5;
    const int lane = tid & 31;
    const int wm   = w >> 2;            // 0..1
    const int wn   = w & 3;             // 0..3
    const int bm   = blockIdx.y * CTM;
    const int bn   = blockIdx.x * CTN;

    // precomputed ldsm row-base offsets (loop-invariant)
    const int khalf = (lane >> 4) * 8;
    uint32_t aoff[4], boff[2];
    #pragma unroll
    for (int mt = 0; mt < 4; mt++)
        aoff[mt] = (wm * 64 + mt * 16 + (lane & 15)) * GST + khalf * 2;
    #pragma unroll
    for (int bt = 0; bt < 2; bt++)
        boff[bt] = TO_B + (wn * 32 + bt * 16 + (lane & 15)) * GST + khalf * 2;

    float acc[4][4][4];
    #pragma unroll
    for (int mt = 0; mt < 4; mt++)
        #pragma unroll
        for (int nt = 0; nt < 4; nt++)
            #pragma unroll
            for (int e = 0; e < 4; e++) acc[mt][nt][e] = 0.f;

    // loader: per stage 128 rows x 128 B per tensor = 1024 segs; 4/thread/tensor
    #define ISSUE(it_, buf_) do {                                              \
        const int k0_ = (it_) * CTK;                                           \
        const uint32_t sb_ = su + (buf_) * STAGE;                              \
        _Pragma("unroll")                                                      \
        for (int t = 0; t < 4; t++) {                                          \
            int u = tid + t * 256;                                             \
            int row = u >> 3, seg = u & 7;                                     \
            uint32_t off = row * GST + seg * 16;                               \
            cp16(sb_ + off,        Ah + (size_t)(bm + row) * 1024 + k0_ + seg * 8); \
            cp16(sb_ + TO_B + off, Bh + (size_t)(bn + row) * 1024 + k0_ + seg * 8); \
        }                                                                      \
    } while (0)

    ISSUE(0, 0);
    CP_COMMIT();

    for (int it = 0; it < GKIT; it++) {
        if (it + 1 < GKIT) {
            ISSUE(it + 1, (it + 1) & 1);
            CP_COMMIT();
            CP_WAIT1();
        } else {
            CP_WAIT0();
        }
        __syncthreads();

        const uint32_t sb = su + (it & 1) * STAGE;

        #pragma unroll
        for (int ks = 0; ks < 4; ks++) {
            const uint32_t kadd = ks * 32;      // ks*16 halves = 32 bytes
            uint32_t bh[8];
            ldsm4(bh + 0, sb + boff[0] + kadd);
            ldsm4(bh + 4, sb + boff[1] + kadd);

            #pragma unroll
            for (int mt = 0; mt < 4; mt++) {
                uint32_t ah[4];
                ldsm4(ah, sb + aoff[mt] + kadd);
                #pragma unroll
                for (int nt = 0; nt < 4; nt++) {
                    const int i0 = 4 * (nt >> 1) + (nt & 1);
                    mma_f16(acc[mt][nt], ah, bh[i0], bh[i0 + 2]);
                }
            }
        }
        __syncthreads();
    }
    #undef ISSUE

    const int erow = bm + wm * 64 + (lane >> 2);

    if (QKV) {
        const int tsel = bn >> 10;              // 0=Q, 1=K, 2=V
        const int cloc = (bn & 1023) + wn * 32;
        __half* Oh = (tsel == 0) ? O0h : (tsel == 1) ? O1h : O2h;
        const bool wlo = (tsel == 0);
        const float scl = (tsel == 0) ? 0.125f : 1.0f;
        #pragma unroll
        for (int nt = 0; nt < 4; nt++) {
            const int col = cloc + nt * 8 + (lane & 3) * 2;
            #pragma unroll
            for (int mt = 0; mt < 4; mt++) {
                #pragma unroll
                for (int rh = 0; rh < 2; rh++) {
                    const size_t row = (size_t)(erow + mt * 16 + rh * 8);
                    const float v0 = acc[mt][nt][2 * rh]     * scl;
                    const float v1 = acc[mt][nt][2 * rh + 1] * scl;
                    const __half h0 = __float2half_rn(v0);
                    const __half h1 = __float2half_rn(v1);
                    *reinterpret_cast<uint32_t*>(Oh + row * 1024 + col) = pack_h2(h0, h1);
                    if (wlo) {
                        const __half l0 = __float2half_rn(v0 - __half2float(h0));
                        const __half l1 = __float2half_rn(v1 - __half2float(h1));
                        *reinterpret_cast<uint32_t*>(O0l + row * 1024 + col) = pack_h2(l0, l1);
                    }
                }
            }
        }
    } else {
        #pragma unroll
        for (int nt = 0; nt < 4; nt++) {
            const int col = bn + wn * 32 + nt * 8 + (lane & 3) * 2;
            const float bx = bias ? bias[col] : 0.f;
            const float by = bias ? bias[col + 1] : 0.f;
            #pragma unroll
            for (int mt = 0; mt < 4; mt++) {
                const int r0 = erow + mt * 16;
                float2 v0 = make_float2(acc[mt][nt][0] + bx, acc[mt][nt][1] + by);
                float2 v1 = make_float2(acc[mt][nt][2] + bx, acc[mt][nt][3] + by);
                *reinterpret_cast<float2*>(C + (size_t)r0 * DOUT + col) = v0;
                *reinterpret_cast<float2*>(C + (size_t)(r0 + 8) * DOUT + col) = v1;
            }
        }
    }
}

// ---------------------------------------------------------------------------
// HMMA flash attention (R14 config — best measured).
// S: 2-term (Q hi/lo, K hi).  PV: 1-term.  Epilogue: fp16 ctx (hi only).
// ---------------------------------------------------------------------------
#define ABQ 128
#define AKV 64
#define AST 72
#define KVT_H (AKV * AST)               // 4608 halves
#define STAGE_H (2 * KVT_H)             // Kh | Vh
#define ASMEM_B (2 * STAGE_H * 2)       // 36864 bytes

__global__ __launch_bounds__(256, 1)
void attn_mma(const __half* __restrict__ Qh, const __half* __restrict__ Ql,
              const __half* __restrict__ Kh, const __half* __restrict__ Vh,
              __half* __restrict__ Ch)
{
    extern __shared__ __align__(16) __half s[];
    const uint32_t sbase = smem_u32(s);

    const int tid  = threadIdx.x;
    const int w    = tid >> 5;
    const int lane = tid & 31;

    const int qt = (int)gridDim.x - 1 - (int)blockIdx.x;   // heavy first
    const int bh = blockIdx.y;
    const int b  = bh >> 4;
    const int h  = bh & 15;

    const size_t rowbase = (size_t)b * SEQ;
    const int    colbase = h * HDIM;
    const int    qbase   = qt * ABQ;
    const int    wq      = qbase + w * 16;

    // ---- stage Q hi/lo, load A fragments ----
    {
        #pragma unroll
        for (int t = 0; t < 4; t++) {
            int u = tid + t * 256;
            int row = u >> 3, seg = u & 7;
            uint4 vh4 = *reinterpret_cast<const uint4*>(
                Qh + (rowbase + qbase + row) * 1024 + colbase + seg * 8);
            uint4 vl4 = *reinterpret_cast<const uint4*>(
                Ql + (rowbase + qbase + row) * 1024 + colbase + seg * 8);
            *reinterpret_cast<uint4*>(s + row * AST + seg * 8) = vh4;
            *reinterpret_cast<uint4*>(s + ABQ * AST + row * AST + seg * 8) = vl4;
        }
    }
    __syncthreads();

    uint32_t qfh[4][4], qfl[4][4];
    {
        const int arow = w * 16 + (lane & 15);
        const int k8   = (lane >> 4) * 8;
        #pragma unroll
        for (int ks = 0; ks < 4; ks++) {
            ldsm4(qfh[ks], sbase + (arow * AST + ks * 16 + k8) * 2);
            ldsm4(qfl[ks], sbase + ((ABQ * AST) + arow * AST + ks * 16 + k8) * 2);
        }
    }
    __syncthreads();

    float ctx[8][4];
    #pragma unroll
    for (int nt = 0; nt < 8; nt++)
        #pragma unroll
        for (int e = 0; e < 4; e++) ctx[nt][e] = 0.f;
    float mrow[2] = {-1e30f, -1e30f};
    float lrow[2] = {0.f, 0.f};

    const int nkt = 2 * qt + 2;

    uint4 rg[4];
    #define AGLD(kt_) do {                                                     \
        const __half* gt0[2] = {Kh, Vh};                                       \
        _Pragma("unroll")                                                      \
        for (int tn = 0; tn < 2; tn++)                                         \
            _Pragma("unroll")                                                  \
            for (int t = 0; t < 2; t++) {                                      \
                int u = tid + t * 256;                                         \
                int row = u >> 3, seg = u & 7;                                 \
                rg[tn * 2 + t] = *reinterpret_cast<const uint4*>(              \
                    gt0[tn] + (rowbase + (kt_) * AKV + row) * 1024             \
                            + colbase + seg * 8);                              \
            }                                                                  \
    } while (0)
    #define ASTS(buf_) do {                                                    \
        __half* sb = s + (buf_) * STAGE_H;                                     \
        _Pragma("unroll")                                                      \
        for (int tn = 0; tn < 2; tn++)                                         \
            _Pragma("unroll")                                                  \
            for (int t = 0; t < 2; t++) {                                      \
                int u = tid + t * 256;                                         \
                int row = u >> 3, seg = u & 7;                                 \
                *reinterpret_cast<uint4*>(sb + tn * KVT_H + row * AST          \
                                          + seg * 8) = rg[tn * 2 + t];         \
            }                                                                  \
    } while (0)

    AGLD(0);
    ASTS(0);
    __syncthreads();

    for (int kt = 0; kt < nkt; kt++) {
        const int buf = kt & 1;
        if (kt + 1 < nkt) AGLD(kt + 1);

        const bool skip = (kt * AKV) > (wq + 15);
        if (!skip) {
            const uint32_t kh_b = sbase + (buf * STAGE_H + 0 * KVT_H) * 2;
            const uint32_t vh_b = sbase + (buf * STAGE_H + 1 * KVT_H) * 2;

            // ---- S = Q K^T (2-term: Q corrected) ----
            float sv[8][4];
            #pragma unroll
            for (int nt = 0; nt < 8; nt++)
                #pragma unroll
                for (int e = 0; e < 4; e++) sv[nt][e] = 0.f;

            const int brow = lane & 15;
            const int k8   = (lane >> 4) * 8;
            #pragma unroll
            for (int ks = 0; ks < 4; ks++) {
                #pragma unroll
                for (int np = 0; np < 4; np++) {
                    uint32_t kh4[4];
                    const uint32_t off = ((np * 16 + brow) * AST + ks * 16 + k8) * 2;
                    ldsm4(kh4, kh_b + off);
                    mma_f16(sv[2 * np],     qfh[ks], kh4[0], kh4[2]);
                    mma_f16(sv[2 * np],     qfl[ks], kh4[0], kh4[2]);
                    mma_f16(sv[2 * np + 1], qfh[ks], kh4[1], kh4[3]);
                    mma_f16(sv[2 * np + 1], qfl[ks], kh4[1], kh4[3]);
                }
            }

            // ---- causal mask ----
            if (kt * AKV + AKV - 1 > wq) {
                const int qr = wq + (lane >> 2);
                #pragma unroll
                for (int nt = 0; nt < 8; nt++) {
                    const int kg0 = kt * AKV + nt * 8 + (lane & 3) * 2;
                    #pragma unroll
                    for (int e = 0; e < 4; e++) {
                        const int qg = qr + ((e >> 1) << 3);
                        const int kg = kg0 + (e & 1);
                        if (kg > qg) sv[nt][e] = -1e30f;
                    }
                }
            }

            // ---- online softmax ----
            float alpha[2];
            #pragma unroll
            for (int rr = 0; rr < 2; rr++) {
                float rmax = -1e30f;
                #pragma unroll
                for (int nt = 0; nt < 8; nt++)
                    rmax = fmaxf(rmax, fmaxf(sv[nt][2 * rr], sv[nt][2 * rr + 1]));
                rmax = fmaxf(rmax, __shfl_xor_sync(0xffffffffu, rmax, 1));
                rmax = fmaxf(rmax, __shfl_xor_sync(0xffffffffu, rmax, 2));
                const float mnew = fmaxf(mrow[rr], rmax);
                alpha[rr] = __expf(mrow[rr] - mnew);
                float rsum = 0.f;
                #pragma unroll
                for (int nt = 0; nt < 8; nt++) {
                    float p0 = __expf(sv[nt][2 * rr]     - mnew);
                    float p1 = __expf(sv[nt][2 * rr + 1] - mnew);
                    sv[nt][2 * rr] = p0; sv[nt][2 * rr + 1] = p1;
                    rsum += p0 + p1;
                }
                rsum += __shfl_xor_sync(0xffffffffu, rsum, 1);
                rsum += __shfl_xor_sync(0xffffffffu, rsum, 2);
                lrow[rr] = lrow[rr] * alpha[rr] + rsum;
                mrow[rr] = mnew;
            }
            #pragma unroll
            for (int nt = 0; nt < 8; nt++) {
                ctx[nt][0] *= alpha[0]; ctx[nt][1] *= alpha[0];
                ctx[nt][2] *= alpha[1]; ctx[nt][3] *= alpha[1];
            }

            // ---- pack P fragments (fp16 hi only) ----
            uint32_t pah[4][4];
            #pragma unroll
            for (int t = 0; t < 4; t++) {
                #pragma unroll
                for (int h2 = 0; h2 < 4; h2++) {
                    const int nt = 2 * t + (h2 >> 1);
                    const int e0 = (h2 & 1) * 2;
                    pah[t][h2] = pack_h2(__float2half_rn(sv[nt][e0]),
                                         __float2half_rn(sv[nt][e0 + 1]));
                }
            }

            // ---- ctx += P V (1-term) ----
            #pragma unroll
            for (int t = 0; t < 4; t++) {
                #pragma unroll
                for (int dp = 0; dp < 4; dp++) {
                    uint32_t vh4[4];
                    const uint32_t off =
                        ((t * 16 + (lane & 15)) * AST + dp * 16 + k8) * 2;
                    ldsm4t(vh4, vh_b + off);
                    mma_f16(ctx[2 * dp],     pah[t], vh4[0], vh4[1]);
                    mma_f16(ctx[2 * dp + 1], pah[t], vh4[2], vh4[3]);
                }
            }
        }

        if (kt + 1 < nkt) ASTS(buf ^ 1);
        __syncthreads();
    }

    // ---- epilogue: ctx /= l, write fp16 hi ----
    #pragma unroll
    for (int rr = 0; rr < 2; rr++) {
        const float inv = 1.f / lrow[rr];
        const size_t row = rowbase + qbase + w * 16 + (lane >> 2) + rr * 8;
        #pragma unroll
        for (int nt = 0; nt < 8; nt++) {
            const int col = colbase + nt * 8 + (lane & 3) * 2;
            *reinterpret_cast<uint32_t*>(Ch + row * 1024 + col) =
                pack_h2(__float2half_rn(ctx[nt][2 * rr] * inv),
                        __float2half_rn(ctx[nt][2 * rr + 1] * inv));
        }
    }
    #undef AGLD
    #undef ASTS
}

// ---------------------------------------------------------------------------
// Launcher
// ---------------------------------------------------------------------------
extern "C" void kernel_launch(void* const* d_in, const int* in_sizes, int n_in,
                              void* d_out, int out_size)
{
    const float* x  = (const float*)d_in[0];
    const float* Wq = (const float*)d_in[1];
    const float* Wk = (const float*)d_in[2];
    const float* Wv = (const float*)d_in[3];
    const float* Wo = (const float*)d_in[4];
    const float* bo = (const float*)d_in[5];
    float* out = (float*)d_out;

    __half *xh, *Wt, *qhh, *qhl, *khh, *vhh, *chh;
    cudaGetSymbolAddress((void**)&xh,  g_xh);
    cudaGetSymbolAddress((void**)&Wt,  g_Wt);
    cudaGetSymbolAddress((void**)&qhh, g_Qh);
    cudaGetSymbolAddress((void**)&qhl, g_Ql);
    cudaGetSymbolAddress((void**)&khh, g_Kh);
    cudaGetSymbolAddress((void**)&vhh, g_Vh);
    cudaGetSymbolAddress((void**)&chh, g_Ch);
    const float** wptrs;
    cudaGetSymbolAddress((void**)&wptrs, g_Wptrs);

    const int n4 = MROWS * DIN / 4;

    // convert x -> fp16
    convert_half_kernel<<<(n4 + 255) / 256, 256>>>(x, xh, n4);

    // transpose the four weight matrices to fp16 [N,K] (one launch)
    set_wptrs_kernel<<<1, 1>>>(Wq, Wk, Wv, Wo);
    dim3 tb(32, 8), tg(32, 32, 4);
    transpose_half_kernel<<<tg, tb>>>(wptrs, Wt);

    // fused QKV GEMM (N = 3072), 1-term fp16, CTK=64
    cudaFuncSetAttribute(gemm_pipe<true>,
                         cudaFuncAttributeMaxDynamicSharedMemorySize, GEMM_SMEM);
    cudaFuncSetAttribute(gemm_pipe<false>,
                         cudaFuncAttributeMaxDynamicSharedMemorySize, GEMM_SMEM);
    dim3 gq(3 * DOUT / CTN, MROWS / CTM);   // (24, 32)
    gemm_pipe<true><<<gq, 256, GEMM_SMEM>>>(xh, Wt, nullptr, nullptr,
                                            qhh, qhl, khh, vhh);

    // HMMA flash attention -> fp16 ctx
    cudaFuncSetAttribute(attn_mma, cudaFuncAttributeMaxDynamicSharedMemorySize,
                         ASMEM_B);
    dim3 attn_grid(SEQ / ABQ, BATCH * NHEADS);   // (16, 32)
    attn_mma<<<attn_grid, 256, ASMEM_B>>>(qhh, qhl, khh, vhh, chh);

    // output projection (1-term ctx, with bias)
    dim3 go(DOUT / CTN, MROWS / CTM);       // (8, 32)
    gemm_pipe<false><<<go, 256, GEMM_SMEM>>>(chh, Wt + 3 * WELEM,
                                             bo, out,
                                             nullptr, nullptr, nullptr, nullptr);
}

// round 17
// speedup vs baseline: 1.0991x; 1.0062x over previous
#include <cuda_runtime.h>
#include <cuda_bf16.h>
#include <cuda_fp16.h>
#include <cstdint>

// Problem constants
#define BATCH   2
#define SEQ     2048
#define DIN     1024
#define DOUT    1024
#define NHEADS  16
#define HDIM    64
#define MROWS   (BATCH * SEQ)        // 4096
#define WELEM   (DIN * DOUT)         // 1M

// ---------------------------------------------------------------------------
// Scratch (device globals — no runtime allocation allowed)
// ---------------------------------------------------------------------------
__device__ __half g_xh[MROWS * DIN];         // x fp16
__device__ __half g_Wt[4 * WELEM];           // transposed weights [N,K], fp16
__device__ __half g_Qh[MROWS * DOUT];
__device__ __half g_Ql[MROWS * DOUT];        // Q lo (S stays 2-term)
__device__ __half g_Kh[MROWS * DOUT];        // K hi only
__device__ __half g_Vh[MROWS * DOUT];        // V hi only
__device__ __half g_Ch[MROWS * DOUT];        // ctx fp16 (hi only)

// ---------------------------------------------------------------------------
// Warp-MMA / async-copy helpers (baseline PTX ISA, no arch-"a" features)
// ---------------------------------------------------------------------------
__device__ __forceinline__ uint32_t smem_u32(const void* p) {
    uint32_t a;
    asm("{ .reg .u64 t; cvta.to.shared.u64 t, %1; cvt.u32.u64 %0, t; }"
        : "=r"(a) : "l"(p));
    return a;
}
__device__ __forceinline__ void ldsm4(uint32_t* r, uint32_t addr) {
    asm volatile("ldmatrix.sync.aligned.m8n8.x4.shared.b16 {%0,%1,%2,%3}, [%4];"
                 : "=r"(r[0]), "=r"(r[1]), "=r"(r[2]), "=r"(r[3]) : "r"(addr));
}
__device__ __forceinline__ void ldsm4t(uint32_t* r, uint32_t addr) {
    asm volatile("ldmatrix.sync.aligned.m8n8.x4.trans.shared.b16 {%0,%1,%2,%3}, [%4];"
                 : "=r"(r[0]), "=r"(r[1]), "=r"(r[2]), "=r"(r[3]) : "r"(addr));
}
__device__ __forceinline__ void mma_f16(float* c, const uint32_t* a,
                                        uint32_t b0, uint32_t b1) {
    asm volatile(
        "mma.sync.aligned.m16n8k16.row.col.f32.f16.f16.f32 "
        "{%0,%1,%2,%3}, {%4,%5,%6,%7}, {%8,%9}, {%0,%1,%2,%3};"
        : "+f"(c[0]), "+f"(c[1]), "+f"(c[2]), "+f"(c[3])
        : "r"(a[0]), "r"(a[1]), "r"(a[2]), "r"(a[3]), "r"(b0), "r"(b1));
}
__device__ __forceinline__ void cp16(uint32_t dst, const void* src) {
    asm volatile("cp.async.cg.shared.global [%0], [%1], 16;"
                 :: "r"(dst), "l"(src));
}
#define CP_COMMIT() asm volatile("cp.async.commit_group;" ::: "memory")
#define CP_WAIT1()  asm volatile("cp.async.wait_group 1;" ::: "memory")
#define CP_WAIT0()  asm volatile("cp.async.wait_group 0;" ::: "memory")

__device__ __forceinline__ uint32_t pack_h2(__half a, __half b) {
    __half2 h = __halves2half2(a, b);
    return *reinterpret_cast<uint32_t*>(&h);
}

// ---------------------------------------------------------------------------
// Convert fp32 -> fp16
// ---------------------------------------------------------------------------
__global__ __launch_bounds__(256)
void convert_half_kernel(const float* __restrict__ in, __half* __restrict__ o, int n4)
{
    int i = blockIdx.x * blockDim.x + threadIdx.x;
    if (i >= n4) return;
    float4 v = reinterpret_cast<const float4*>(in)[i];
    uint2 p = make_uint2(pack_h2(__float2half_rn(v.x), __float2half_rn(v.y)),
                         pack_h2(__float2half_rn(v.z), __float2half_rn(v.w)));
    reinterpret_cast<uint2*>(o)[i] = p;
}

// ---------------------------------------------------------------------------
// Transpose: W [K,N] fp32 row-major -> Wt [N,K] fp16 (4 matrices via z)
// ---------------------------------------------------------------------------
__global__ __launch_bounds__(256)
void transpose_half_kernel(const float* const* __restrict__ Ws,
                           __half* __restrict__ T)
{
    __shared__ float t[32][33];
    const float* W = Ws[blockIdx.z];
    __half* To = T + (size_t)blockIdx.z * WELEM;
    int bx = blockIdx.x * 32;   // N
    int by = blockIdx.y * 32;   // K
    int x = threadIdx.x, y = threadIdx.y;
    #pragma unroll
    for (int j = 0; j < 32; j += 8)
        t[y + j][x] = W[(size_t)(by + y + j) * DOUT + bx + x];
    __syncthreads();
    #pragma unroll
    for (int j = 0; j < 32; j += 8)
        To[(size_t)(bx + y + j) * DIN + by + x] = __float2half_rn(t[x][y + j]);
}
__device__ const float* g_Wptrs[4];
__global__ void set_wptrs_kernel(const float* a, const float* b,
                                 const float* c, const float* d)
{
    g_Wptrs[0] = a; g_Wptrs[1] = b; g_Wptrs[2] = c; g_Wptrs[3] = d;
}

// ---------------------------------------------------------------------------
// 2-stage cp.async HMMA GEMM, 1-term fp16.
// 128-thread CTA, 4 warps (2x2), warp tile 64x64, CTA 128x128, K-tile 64.
// smem row stride 144 B — ldsm conflict-free.
// QKV=true : fused N=3072; epilogue emits Q hi/lo (x0.125), K hi, V hi.
// QKV=false: fp32 + bias epilogue (output projection).
// ---------------------------------------------------------------------------
#define CTM 128
#define CTN 128
#define CTK 64
#define GKIT (DIN / CTK)             // 16
#define GST  144                     // smem row stride (bytes)
#define TENB (128 * GST)             // 18432 bytes per tensor tile
#define TO_B TENB
#define STAGE (2 * TENB)             // 36864
#define GEMM_SMEM (2 * STAGE)        // 73728

template<bool QKV>
__global__ __launch_bounds__(128, 2)
void gemm_pipe(const __half* __restrict__ Ah, const __half* __restrict__ Bh,
               const float* __restrict__ bias, float* __restrict__ C,
               __half* __restrict__ O0h, __half* __restrict__ O0l,
               __half* __restrict__ O1h, __half* __restrict__ O2h)
{
    extern __shared__ __align__(16) char sm_raw[];
    const uint32_t su = smem_u32(sm_raw);

    const int tid  = threadIdx.x;
    const int w    = tid >> 5;
    const int lane = tid & 31;
    const int wm   = w >> 1;            // 0..1 (M)
    const int wn   = w & 1;             // 0..1 (N)
    const int bm   = blockIdx.y * CTM;
    const int bn   = blockIdx.x * CTN;

    // precomputed ldsm row-base offsets (loop-invariant)
    const int khalf = (lane >> 4) * 8;
    uint32_t aoff[4], boff[4];
    #pragma unroll
    for (int mt = 0; mt < 4; mt++)
        aoff[mt] = (wm * 64 + mt * 16 + (lane & 15)) * GST + khalf * 2;
    #pragma unroll
    for (int bt = 0; bt < 4; bt++)
        boff[bt] = TO_B + (wn * 64 + bt * 16 + (lane & 15)) * GST + khalf * 2;

    float acc[4][8][4];
    #pragma unroll
    for (int mt = 0; mt < 4; mt++)
        #pragma unroll
        for (int nt = 0; nt < 8; nt++)
            #pragma unroll
            for (int e = 0; e < 4; e++) acc[mt][nt][e] = 0.f;

    // loader: per stage 2 tensors x 128 rows x 8 segs = 2048; 16 cp/thread
    #define ISSUE(it_, buf_) do {                                              \
        const int k0_ = (it_) * CTK;                                           \
        const uint32_t sb_ = su + (buf_) * STAGE;                              \
        _Pragma("unroll")                                                      \
        for (int t = 0; t < 8; t++) {                                          \
            int u = tid + t * 128;                                             \
            int row = u >> 3, seg = u & 7;                                     \
            uint32_t off = row * GST + seg * 16;                               \
            cp16(sb_ + off,        Ah + (size_t)(bm + row) * 1024 + k0_ + seg * 8); \
            cp16(sb_ + TO_B + off, Bh + (size_t)(bn + row) * 1024 + k0_ + seg * 8); \
        }                                                                      \
    } while (0)

    ISSUE(0, 0);
    CP_COMMIT();

    for (int it = 0; it < GKIT; it++) {
        if (it + 1 < GKIT) {
            ISSUE(it + 1, (it + 1) & 1);
            CP_COMMIT();
            CP_WAIT1();
        } else {
            CP_WAIT0();
        }
        __syncthreads();

        const uint32_t sb = su + (it & 1) * STAGE;

        #pragma unroll
        for (int ks = 0; ks < 4; ks++) {
            const uint32_t kadd = ks * 32;      // ks*16 halves = 32 bytes
            uint32_t bh[16];
            ldsm4(bh +  0, sb + boff[0] + kadd);
            ldsm4(bh +  4, sb + boff[1] + kadd);
            ldsm4(bh +  8, sb + boff[2] + kadd);
            ldsm4(bh + 12, sb + boff[3] + kadd);

            #pragma unroll
            for (int mt = 0; mt < 4; mt++) {
                uint32_t ah[4];
                ldsm4(ah, sb + aoff[mt] + kadd);
                #pragma unroll
                for (int nt = 0; nt < 8; nt++) {
                    const int i0 = 4 * (nt >> 1) + (nt & 1);
                    mma_f16(acc[mt][nt], ah, bh[i0], bh[i0 + 2]);
                }
            }
        }
        __syncthreads();
    }
    #undef ISSUE

    const int erow = bm + wm * 64 + (lane >> 2);

    if (QKV) {
        const int tsel = bn >> 10;              // 0=Q, 1=K, 2=V
        const int cloc = (bn & 1023) + wn * 64;
        __half* Oh = (tsel == 0) ? O0h : (tsel == 1) ? O1h : O2h;
        const bool wlo = (tsel == 0);
        const float scl = (tsel == 0) ? 0.125f : 1.0f;
        #pragma unroll
        for (int nt = 0; nt < 8; nt++) {
            const int col = cloc + nt * 8 + (lane & 3) * 2;
            #pragma unroll
            for (int mt = 0; mt < 4; mt++) {
                #pragma unroll
                for (int rh = 0; rh < 2; rh++) {
                    const size_t row = (size_t)(erow + mt * 16 + rh * 8);
                    const float v0 = acc[mt][nt][2 * rh]     * scl;
                    const float v1 = acc[mt][nt][2 * rh + 1] * scl;
                    const __half h0 = __float2half_rn(v0);
                    const __half h1 = __float2half_rn(v1);
                    *reinterpret_cast<uint32_t*>(Oh + row * 1024 + col) = pack_h2(h0, h1);
                    if (wlo) {
                        const __half l0 = __float2half_rn(v0 - __half2float(h0));
                        const __half l1 = __float2half_rn(v1 - __half2float(h1));
                        *reinterpret_cast<uint32_t*>(O0l + row * 1024 + col) = pack_h2(l0, l1);
                    }
                }
            }
        }
    } else {
        #pragma unroll
        for (int nt = 0; nt < 8; nt++) {
            const int col = bn + wn * 64 + nt * 8 + (lane & 3) * 2;
            const float bx = bias ? bias[col] : 0.f;
            const float by = bias ? bias[col + 1] : 0.f;
            #pragma unroll
            for (int mt = 0; mt < 4; mt++) {
                const int r0 = erow + mt * 16;
                float2 v0 = make_float2(acc[mt][nt][0] + bx, acc[mt][nt][1] + by);
                float2 v1 = make_float2(acc[mt][nt][2] + bx, acc[mt][nt][3] + by);
                *reinterpret_cast<float2*>(C + (size_t)r0 * DOUT + col) = v0;
                *reinterpret_cast<float2*>(C + (size_t)(r0 + 8) * DOUT + col) = v1;
            }
        }
    }
}

// ---------------------------------------------------------------------------
// HMMA flash attention (R14 config — best measured).
// S: 2-term (Q hi/lo, K hi).  PV: 1-term.  Epilogue: fp16 ctx (hi only).
// ---------------------------------------------------------------------------
#define ABQ 128
#define AKV 64
#define AST 72
#define KVT_H (AKV * AST)               // 4608 halves
#define STAGE_H (2 * KVT_H)             // Kh | Vh
#define ASMEM_B (2 * STAGE_H * 2)       // 36864 bytes

__global__ __launch_bounds__(256, 1)
void attn_mma(const __half* __restrict__ Qh, const __half* __restrict__ Ql,
              const __half* __restrict__ Kh, const __half* __restrict__ Vh,
              __half* __restrict__ Ch)
{
    extern __shared__ __align__(16) __half s[];
    const uint32_t sbase = smem_u32(s);

    const int tid  = threadIdx.x;
    const int w    = tid >> 5;
    const int lane = tid & 31;

    const int qt = (int)gridDim.x - 1 - (int)blockIdx.x;   // heavy first
    const int bh = blockIdx.y;
    const int b  = bh >> 4;
    const int h  = bh & 15;

    const size_t rowbase = (size_t)b * SEQ;
    const int    colbase = h * HDIM;
    const int    qbase   = qt * ABQ;
    const int    wq      = qbase + w * 16;

    // ---- stage Q hi/lo, load A fragments ----
    {
        #pragma unroll
        for (int t = 0; t < 4; t++) {
            int u = tid + t * 256;
            int row = u >> 3, seg = u & 7;
            uint4 vh4 = *reinterpret_cast<const uint4*>(
                Qh + (rowbase + qbase + row) * 1024 + colbase + seg * 8);
            uint4 vl4 = *reinterpret_cast<const uint4*>(
                Ql + (rowbase + qbase + row) * 1024 + colbase + seg * 8);
            *reinterpret_cast<uint4*>(s + row * AST + seg * 8) = vh4;
            *reinterpret_cast<uint4*>(s + ABQ * AST + row * AST + seg * 8) = vl4;
        }
    }
    __syncthreads();

    uint32_t qfh[4][4], qfl[4][4];
    {
        const int arow = w * 16 + (lane & 15);
        const int k8   = (lane >> 4) * 8;
        #pragma unroll
        for (int ks = 0; ks < 4; ks++) {
            ldsm4(qfh[ks], sbase + (arow * AST + ks * 16 + k8) * 2);
            ldsm4(qfl[ks], sbase + ((ABQ * AST) + arow * AST + ks * 16 + k8) * 2);
        }
    }
    __syncthreads();

    float ctx[8][4];
    #pragma unroll
    for (int nt = 0; nt < 8; nt++)
        #pragma unroll
        for (int e = 0; e < 4; e++) ctx[nt][e] = 0.f;
    float mrow[2] = {-1e30f, -1e30f};
    float lrow[2] = {0.f, 0.f};

    const int nkt = 2 * qt + 2;

    uint4 rg[4];
    #define AGLD(kt_) do {                                                     \
        const __half* gt0[2] = {Kh, Vh};                                       \
        _Pragma("unroll")                                                      \
        for (int tn = 0; tn < 2; tn++)                                         \
            _Pragma("unroll")                                                  \
            for (int t = 0; t < 2; t++) {                                      \
                int u = tid + t * 256;                                         \
                int row = u >> 3, seg = u & 7;                                 \
                rg[tn * 2 + t] = *reinterpret_cast<const uint4*>(              \
                    gt0[tn] + (rowbase + (kt_) * AKV + row) * 1024             \
                            + colbase + seg * 8);                              \
            }                                                                  \
    } while (0)
    #define ASTS(buf_) do {                                                    \
        __half* sb = s + (buf_) * STAGE_H;                                     \
        _Pragma("unroll")                                                      \
        for (int tn = 0; tn < 2; tn++)                                         \
            _Pragma("unroll")                                                  \
            for (int t = 0; t < 2; t++) {                                      \
                int u = tid + t * 256;                                         \
                int row = u >> 3, seg = u & 7;                                 \
                *reinterpret_cast<uint4*>(sb + tn * KVT_H + row * AST          \
                                          + seg * 8) = rg[tn * 2 + t];         \
            }                                                                  \
    } while (0)

    AGLD(0);
    ASTS(0);
    __syncthreads();

    for (int kt = 0; kt < nkt; kt++) {
        const int buf = kt & 1;
        if (kt + 1 < nkt) AGLD(kt + 1);

        const bool skip = (kt * AKV) > (wq + 15);
        if (!skip) {
            const uint32_t kh_b = sbase + (buf * STAGE_H + 0 * KVT_H) * 2;
            const uint32_t vh_b = sbase + (buf * STAGE_H + 1 * KVT_H) * 2;

            // ---- S = Q K^T (2-term: Q corrected) ----
            float sv[8][4];
            #pragma unroll
            for (int nt = 0; nt < 8; nt++)
                #pragma unroll
                for (int e = 0; e < 4; e++) sv[nt][e] = 0.f;

            const int brow = lane & 15;
            const int k8   = (lane >> 4) * 8;
            #pragma unroll
            for (int ks = 0; ks < 4; ks++) {
                #pragma unroll
                for (int np = 0; np < 4; np++) {
                    uint32_t kh4[4];
                    const uint32_t off = ((np * 16 + brow) * AST + ks * 16 + k8) * 2;
                    ldsm4(kh4, kh_b + off);
                    mma_f16(sv[2 * np],     qfh[ks], kh4[0], kh4[2]);
                    mma_f16(sv[2 * np],     qfl[ks], kh4[0], kh4[2]);
                    mma_f16(sv[2 * np + 1], qfh[ks], kh4[1], kh4[3]);
                    mma_f16(sv[2 * np + 1], qfl[ks], kh4[1], kh4[3]);
                }
            }

            // ---- causal mask ----
            if (kt * AKV + AKV - 1 > wq) {
                const int qr = wq + (lane >> 2);
                #pragma unroll
                for (int nt = 0; nt < 8; nt++) {
                    const int kg0 = kt * AKV + nt * 8 + (lane & 3) * 2;
                    #pragma unroll
                    for (int e = 0; e < 4; e++) {
                        const int qg = qr + ((e >> 1) << 3);
                        const int kg = kg0 + (e & 1);
                        if (kg > qg) sv[nt][e] = -1e30f;
                    }
                }
            }

            // ---- online softmax ----
            float alpha[2];
            #pragma unroll
            for (int rr = 0; rr < 2; rr++) {
                float rmax = -1e30f;
                #pragma unroll
                for (int nt = 0; nt < 8; nt++)
                    rmax = fmaxf(rmax, fmaxf(sv[nt][2 * rr], sv[nt][2 * rr + 1]));
                rmax = fmaxf(rmax, __shfl_xor_sync(0xffffffffu, rmax, 1));
                rmax = fmaxf(rmax, __shfl_xor_sync(0xffffffffu, rmax, 2));
                const float mnew = fmaxf(mrow[rr], rmax);
                alpha[rr] = __expf(mrow[rr] - mnew);
                float rsum = 0.f;
                #pragma unroll
                for (int nt = 0; nt < 8; nt++) {
                    float p0 = __expf(sv[nt][2 * rr]     - mnew);
                    float p1 = __expf(sv[nt][2 * rr + 1] - mnew);
                    sv[nt][2 * rr] = p0; sv[nt][2 * rr + 1] = p1;
                    rsum += p0 + p1;
                }
                rsum += __shfl_xor_sync(0xffffffffu, rsum, 1);
                rsum += __shfl_xor_sync(0xffffffffu, rsum, 2);
                lrow[rr] = lrow[rr] * alpha[rr] + rsum;
                mrow[rr] = mnew;
            }
            #pragma unroll
            for (int nt = 0; nt < 8; nt++) {
                ctx[nt][0] *= alpha[0]; ctx[nt][1] *= alpha[0];
                ctx[nt][2] *= alpha[1]; ctx[nt][3] *= alpha[1];
            }

            // ---- pack P fragments (fp16 hi only) ----
            uint32_t pah[4][4];
            #pragma unroll
            for (int t = 0; t < 4; t++) {
                #pragma unroll
                for (int h2 = 0; h2 < 4; h2++) {
                    const int nt = 2 * t + (h2 >> 1);
                    const int e0 = (h2 & 1) * 2;
                    pah[t][h2] = pack_h2(__float2half_rn(sv[nt][e0]),
                                         __float2half_rn(sv[nt][e0 + 1]));
                }
            }

            // ---- ctx += P V (1-term) ----
            #pragma unroll
            for (int t = 0; t < 4; t++) {
                #pragma unroll
                for (int dp = 0; dp < 4; dp++) {
                    uint32_t vh4[4];
                    const uint32_t off =
                        ((t * 16 + (lane & 15)) * AST + dp * 16 + k8) * 2;
                    ldsm4t(vh4, vh_b + off);
                    mma_f16(ctx[2 * dp],     pah[t], vh4[0], vh4[1]);
                    mma_f16(ctx[2 * dp + 1], pah[t], vh4[2], vh4[3]);
                }
            }
        }

        if (kt + 1 < nkt) ASTS(buf ^ 1);
        __syncthreads();
    }

    // ---- epilogue: ctx /= l, write fp16 hi ----
    #pragma unroll
    for (int rr = 0; rr < 2; rr++) {
        const float inv = 1.f / lrow[rr];
        const size_t row = rowbase + qbase + w * 16 + (lane >> 2) + rr * 8;
        #pragma unroll
        for (int nt = 0; nt < 8; nt++) {
            const int col = colbase + nt * 8 + (lane & 3) * 2;
            *reinterpret_cast<uint32_t*>(Ch + row * 1024 + col) =
                pack_h2(__float2half_rn(ctx[nt][2 * rr] * inv),
                        __float2half_rn(ctx[nt][2 * rr + 1] * inv));
        }
    }
    #undef AGLD
    #undef ASTS
}

// ---------------------------------------------------------------------------
// Launcher
// ---------------------------------------------------------------------------
extern "C" void kernel_launch(void* const* d_in, const int* in_sizes, int n_in,
                              void* d_out, int out_size)
{
    const float* x  = (const float*)d_in[0];
    const float* Wq = (const float*)d_in[1];
    const float* Wk = (const float*)d_in[2];
    const float* Wv = (const float*)d_in[3];
    const float* Wo = (const float*)d_in[4];
    const float* bo = (const float*)d_in[5];
    float* out = (float*)d_out;

    __half *xh, *Wt, *qhh, *qhl, *khh, *vhh, *chh;
    cudaGetSymbolAddress((void**)&xh,  g_xh);
    cudaGetSymbolAddress((void**)&Wt,  g_Wt);
    cudaGetSymbolAddress((void**)&qhh, g_Qh);
    cudaGetSymbolAddress((void**)&qhl, g_Ql);
    cudaGetSymbolAddress((void**)&khh, g_Kh);
    cudaGetSymbolAddress((void**)&vhh, g_Vh);
    cudaGetSymbolAddress((void**)&chh, g_Ch);
    const float** wptrs;
    cudaGetSymbolAddress((void**)&wptrs, g_Wptrs);

    const int n4 = MROWS * DIN / 4;

    // convert x -> fp16
    convert_half_kernel<<<(n4 + 255) / 256, 256>>>(x, xh, n4);

    // transpose the four weight matrices to fp16 [N,K] (one launch)
    set_wptrs_kernel<<<1, 1>>>(Wq, Wk, Wv, Wo);
    dim3 tb(32, 8), tg(32, 32, 4);
    transpose_half_kernel<<<tg, tb>>>(wptrs, Wt);

    // fused QKV GEMM (N = 3072), 1-term fp16, CTK=64, 64x64 warp tiles
    cudaFuncSetAttribute(gemm_pipe<true>,
                         cudaFuncAttributeMaxDynamicSharedMemorySize, GEMM_SMEM);
    cudaFuncSetAttribute(gemm_pipe<false>,
                         cudaFuncAttributeMaxDynamicSharedMemorySize, GEMM_SMEM);
    dim3 gq(3 * DOUT / CTN, MROWS / CTM);   // (24, 32)
    gemm_pipe<true><<<gq, 128, GEMM_SMEM>>>(xh, Wt, nullptr, nullptr,
                                            qhh, qhl, khh, vhh);

    // HMMA flash attention -> fp16 ctx
    cudaFuncSetAttribute(attn_mma, cudaFuncAttributeMaxDynamicSharedMemorySize,
                         ASMEM_B);
    dim3 attn_grid(SEQ / ABQ, BATCH * NHEADS);   // (16, 32)
    attn_mma<<<attn_grid, 256, ASMEM_B>>>(qhh, qhl, khh, vhh, chh);

    // output projection (1-term ctx, with bias)
    dim3 go(DOUT / CTN, MROWS / CTM);       // (8, 32)
    gemm_pipe<false><<<go, 128, GEMM_SMEM>>>(chh, Wt + 3 * WELEM,
                                             bo, out,
                                             nullptr, nullptr, nullptr, nullptr);
}